// round 5
// baseline (speedup 1.0000x reference)
#include <cuda_runtime.h>
#include <cstdint>

#define NNODES 100000
#define HIDDIM 128
#define INDIM  256
#define NF ((long)NNODES * HIDDIM)        // 12,800,000 floats per buffer

// One scratch pool, float4 type guarantees 16B alignment. 3 buffers: h1, z1, h2.
__device__ float4 g_scratch[3 * NF / 4];
__device__ int    g_deg[NNODES];
__device__ float  g_dinv[NNODES];

__device__ __forceinline__ float* scr(long off) {
    return reinterpret_cast<float*>(g_scratch) + off;
}

#define OFF_H1 ((long)0)
#define OFF_Z1 (NF)
#define OFF_H2 (2 * NF)

// ---------------------------------------------------------------------------
// degree / norm
// ---------------------------------------------------------------------------
__global__ void zero_deg_kernel(int n) {
    int i = blockIdx.x * blockDim.x + threadIdx.x;
    if (i < n) g_deg[i] = 0;
}

// edge_index is int32 (JAX default x64-disabled downcasts int64 -> int32)
__global__ void count_deg_kernel(const int* __restrict__ ei, int E) {
    int e = blockIdx.x * blockDim.x + threadIdx.x;
    if (e < E) {
        int c = ei[E + e];   // col = edge_index[1]
        atomicAdd(&g_deg[c], 1);
    }
}

__global__ void dinv_kernel(int n) {
    int i = blockIdx.x * blockDim.x + threadIdx.x;
    if (i < n) {
        // deg in reference = in-degree + 1 (self loop); always > 0
        g_dinv[i] = rsqrtf((float)(g_deg[i] + 1));
    }
}

// ---------------------------------------------------------------------------
// GEMM: C[M,128] = A[M,K] @ B[K,128] (+ bias). BM=64 BN=128 BK=16, TM=8 TN=4.
// A/C selected from external pointer (if non-null) or scratch offset.
// ---------------------------------------------------------------------------
__global__ __launch_bounds__(256) void gemm128_kernel(
    const float* __restrict__ Aext, long aoff,
    const float* __restrict__ B, const float* __restrict__ bias,
    float* __restrict__ Cext, long coff, int M, int K)
{
    const float* A = Aext ? Aext : scr(aoff);
    float*       C = Cext ? Cext : scr(coff);

    const int BM = 64, BN = 128, BK = 16, TM = 8, TN = 4;
    __shared__ float As[BK][BM + 1];
    __shared__ float Bs[BK][BN];

    int tid = threadIdx.x;
    int tx = tid & 31;        // 32 col-groups of 4 -> 128 cols
    int ty = tid >> 5;        // 8 row-groups of 8 -> 64 rows
    int m0 = blockIdx.x * BM;

    float acc[TM][TN];
#pragma unroll
    for (int r = 0; r < TM; r++)
#pragma unroll
        for (int c = 0; c < TN; c++) acc[r][c] = 0.f;

    for (int k0 = 0; k0 < K; k0 += BK) {
        // load A tile (transposed into smem)
        for (int i = tid; i < BM * BK; i += 256) {
            int m = i >> 4, k = i & 15;
            int gm = m0 + m;
            As[k][m] = (gm < M) ? A[(size_t)gm * K + k0 + k] : 0.f;
        }
        // load B tile
        for (int i = tid; i < BK * BN; i += 256) {
            int k = i >> 7, n = i & 127;
            Bs[k][n] = B[(size_t)(k0 + k) * BN + n];
        }
        __syncthreads();

#pragma unroll
        for (int k = 0; k < BK; k++) {
            float a[TM], bv[TN];
#pragma unroll
            for (int r = 0; r < TM; r++) a[r] = As[k][ty * TM + r];
#pragma unroll
            for (int c = 0; c < TN; c++) bv[c] = Bs[k][tx * TN + c];
#pragma unroll
            for (int r = 0; r < TM; r++)
#pragma unroll
                for (int c = 0; c < TN; c++) acc[r][c] += a[r] * bv[c];
        }
        __syncthreads();
    }

#pragma unroll
    for (int r = 0; r < TM; r++) {
        int gm = m0 + ty * TM + r;
        if (gm < M) {
#pragma unroll
            for (int c = 0; c < TN; c++) {
                float v = acc[r][c];
                if (bias) v += bias[tx * TN + c];
                C[(size_t)gm * BN + tx * TN + c] = v;
            }
        }
    }
}

// ---------------------------------------------------------------------------
// init agg: agg[i,f] = h[i,f] * dinv[i]^2 + b[f]   (self-loop + bias)
// ---------------------------------------------------------------------------
__global__ void init_agg_kernel(long hoff, const float* __restrict__ b,
                                float* __restrict__ aggext, long aggoff, int n)
{
    const float* h  = scr(hoff);
    float* agg      = aggext ? aggext : scr(aggoff);
    size_t idx = (size_t)blockIdx.x * blockDim.x + threadIdx.x;
    if (idx < (size_t)n * HIDDIM) {
        int i = (int)(idx >> 7);
        int f = (int)(idx & 127);
        float d = g_dinv[i];
        agg[idx] = h[idx] * d * d + b[f];
    }
}

// ---------------------------------------------------------------------------
// edge propagate: one warp per edge; lane handles 4 features (float4 gather,
// 4 float atomic adds -> RED.E.ADD, no return value).
// ---------------------------------------------------------------------------
__global__ __launch_bounds__(256) void edge_prop_kernel(
    long hoff, const int* __restrict__ ei, int E,
    float* __restrict__ aggext, long aggoff)
{
    const float* h = scr(hoff);
    float* agg     = aggext ? aggext : scr(aggoff);

    int warp = blockIdx.x * (blockDim.x >> 5) + (threadIdx.x >> 5);
    if (warp >= E) return;
    int lane = threadIdx.x & 31;

    int r = ei[warp];
    int c = ei[E + warp];
    float nrm = g_dinv[r] * g_dinv[c];

    float4 v = reinterpret_cast<const float4*>(h + (size_t)r * HIDDIM)[lane];
    float* dst = agg + (size_t)c * HIDDIM + lane * 4;
    atomicAdd(dst + 0, v.x * nrm);
    atomicAdd(dst + 1, v.y * nrm);
    atomicAdd(dst + 2, v.z * nrm);
    atomicAdd(dst + 3, v.w * nrm);
}

// ---------------------------------------------------------------------------
// launch — kernels only, no runtime API calls
// ---------------------------------------------------------------------------
extern "C" void kernel_launch(void* const* d_in, const int* in_sizes, int n_in,
                              void* d_out, int out_size)
{
    const float* x  = (const float*)d_in[0];
    const int*   ei = (const int*)d_in[1];       // int32 edge index
    const float* W1 = (const float*)d_in[2];
    const float* b1 = (const float*)d_in[3];
    const float* W2 = (const float*)d_in[4];
    const float* b2 = (const float*)d_in[5];
    const float* Wp = (const float*)d_in[6];
    const float* bp = (const float*)d_in[7];

    int N = in_sizes[0] / INDIM;          // 100000
    int E = in_sizes[1] / 2;              // 1600000

    float* z    = (float*)d_out;                       // first output: z2 [N,128]
    float* proj = z + (size_t)N * HIDDIM;              // second output

    const int T = 256;
    int nBlocksN    = (N + T - 1) / T;
    int nBlocksE    = (E + T - 1) / T;
    int nBlocksNF   = (int)(((size_t)N * HIDDIM + T - 1) / T);
    int nBlocksGemm = (N + 63) / 64;
    int nBlocksEdge = (E + 7) / 8;        // 8 warps per block

    // degrees + normalization (shared by both layers)
    zero_deg_kernel<<<nBlocksN, T>>>(N);
    count_deg_kernel<<<nBlocksE, T>>>(ei, E);
    dinv_kernel<<<nBlocksN, T>>>(N);

    // layer 1: h1 = x @ W1 ; z1 = propagate(h1) + b1
    gemm128_kernel<<<nBlocksGemm, T>>>(x, 0, W1, nullptr, nullptr, OFF_H1, N, INDIM);
    init_agg_kernel<<<nBlocksNF, T>>>(OFF_H1, b1, nullptr, OFF_Z1, N);
    edge_prop_kernel<<<nBlocksEdge, T>>>(OFF_H1, ei, E, nullptr, OFF_Z1);

    // layer 2: h2 = z1 @ W2 ; z = propagate(h2) + b2   (z written to d_out)
    gemm128_kernel<<<nBlocksGemm, T>>>(nullptr, OFF_Z1, W2, nullptr, nullptr, OFF_H2, N, HIDDIM);
    init_agg_kernel<<<nBlocksNF, T>>>(OFF_H2, b2, z, 0, N);
    edge_prop_kernel<<<nBlocksEdge, T>>>(OFF_H2, ei, E, z, 0);

    // projection head: proj = z @ Wp + bp
    gemm128_kernel<<<nBlocksGemm, T>>>(z, 0, Wp, bp, proj, 0, N, HIDDIM);
}

// round 6
// speedup vs baseline: 1.7260x; 1.7260x over previous
#include <cuda_runtime.h>
#include <cstdint>

#define NNODES 100000
#define HIDDIM 128
#define INDIM  256
#define NF ((long)NNODES * HIDDIM)        // 12,800,000 floats per buffer

// One scratch pool, float4 type guarantees 16B alignment. 3 buffers: h1, z1, h2.
__device__ float4 g_scratch[3 * NF / 4];
__device__ int    g_deg[NNODES];
__device__ float  g_dinv[NNODES];

__device__ __forceinline__ float* scr(long off) {
    return reinterpret_cast<float*>(g_scratch) + off;
}

#define OFF_H1 ((long)0)
#define OFF_Z1 (NF)
#define OFF_H2 (2 * NF)

// ---------------------------------------------------------------------------
// degree / norm
// ---------------------------------------------------------------------------
__global__ void zero_deg_kernel(int n) {
    int i = blockIdx.x * blockDim.x + threadIdx.x;
    if (i < n) g_deg[i] = 0;
}

// edge_index is int32 (JAX x64 disabled)
__global__ void count_deg_kernel(const int* __restrict__ ei, int E) {
    int e = blockIdx.x * blockDim.x + threadIdx.x;
    if (e < E) atomicAdd(&g_deg[ei[E + e]], 1);
}

__global__ void dinv_kernel(int n) {
    int i = blockIdx.x * blockDim.x + threadIdx.x;
    if (i < n) g_dinv[i] = rsqrtf((float)(g_deg[i] + 1));
}

// ---------------------------------------------------------------------------
// GEMM: C[M,128] = A[M,K] @ B[K,128]. BM=128 BN=128 BK=8, 8x8 reg tile.
// Fused epilogue:
//   C[m][n]   = acc (+ cBias[n] if cBias)
//   agg[m][n] = acc * dinv[m]^2 + aggBias[n]      (if agg != null)
// ---------------------------------------------------------------------------
__global__ __launch_bounds__(256, 2) void gemm128_kernel(
    const float* __restrict__ Aext, long aoff,
    const float* __restrict__ B,
    float* __restrict__ Cext, long coff,
    const float* __restrict__ cBias,
    float* __restrict__ aggExt, long aggoff, int useAgg,
    const float* __restrict__ aggBias,
    int M, int K)
{
    const float* A = Aext ? Aext : scr(aoff);
    float*       C = Cext ? Cext : scr(coff);
    float*     agg = useAgg ? (aggExt ? aggExt : scr(aggoff)) : nullptr;

    const int BM = 128, BN = 128, BK = 8;
    __shared__ float As[BK][BM + 4];
    __shared__ float Bs[BK][BN];

    int tid = threadIdx.x;
    int tx = tid & 15;          // 16 col groups of 8
    int ty = tid >> 4;          // 16 row groups of 8
    int m0 = blockIdx.x * BM;

    // A-load mapping: thread loads float4 of K for one row
    int la_m = tid >> 1;              // 0..127
    int la_k = (tid & 1) * 4;         // 0 or 4
    // B-load mapping: thread loads float4 of N for one k
    int lb_k = tid >> 5;              // 0..7
    int lb_n = (tid & 31) * 4;        // 0..124

    float acc[8][8];
#pragma unroll
    for (int r = 0; r < 8; r++)
#pragma unroll
        for (int c = 0; c < 8; c++) acc[r][c] = 0.f;

    for (int k0 = 0; k0 < K; k0 += BK) {
        // A tile -> transposed smem
        {
            int gm = m0 + la_m;
            float4 v = make_float4(0.f, 0.f, 0.f, 0.f);
            if (gm < M)
                v = *reinterpret_cast<const float4*>(&A[(size_t)gm * K + k0 + la_k]);
            As[la_k + 0][la_m] = v.x;
            As[la_k + 1][la_m] = v.y;
            As[la_k + 2][la_m] = v.z;
            As[la_k + 3][la_m] = v.w;
        }
        // B tile
        {
            float4 v = *reinterpret_cast<const float4*>(&B[(size_t)(k0 + lb_k) * BN + lb_n]);
            *reinterpret_cast<float4*>(&Bs[lb_k][lb_n]) = v;
        }
        __syncthreads();

#pragma unroll
        for (int k = 0; k < BK; k++) {
            float a[8], bv[8];
            *reinterpret_cast<float4*>(a)      = *reinterpret_cast<const float4*>(&As[k][ty * 8]);
            *reinterpret_cast<float4*>(a + 4)  = *reinterpret_cast<const float4*>(&As[k][ty * 8 + 4]);
            *reinterpret_cast<float4*>(bv)     = *reinterpret_cast<const float4*>(&Bs[k][tx * 8]);
            *reinterpret_cast<float4*>(bv + 4) = *reinterpret_cast<const float4*>(&Bs[k][tx * 8 + 4]);
#pragma unroll
            for (int r = 0; r < 8; r++)
#pragma unroll
                for (int c = 0; c < 8; c++) acc[r][c] += a[r] * bv[c];
        }
        __syncthreads();
    }

#pragma unroll
    for (int r = 0; r < 8; r++) {
        int gm = m0 + ty * 8 + r;
        if (gm >= M) break;
        float d = 0.f;
        if (agg) { d = g_dinv[gm]; d = d * d; }
        size_t rowOff = (size_t)gm * BN + tx * 8;
#pragma unroll
        for (int c4 = 0; c4 < 2; c4++) {
            float4 v;
            v.x = acc[r][c4 * 4 + 0];
            v.y = acc[r][c4 * 4 + 1];
            v.z = acc[r][c4 * 4 + 2];
            v.w = acc[r][c4 * 4 + 3];
            if (cBias) {
                const float4 bb = *reinterpret_cast<const float4*>(&cBias[tx * 8 + c4 * 4]);
                v.x += bb.x; v.y += bb.y; v.z += bb.z; v.w += bb.w;
            }
            *reinterpret_cast<float4*>(&C[rowOff + c4 * 4]) = v;
            if (agg) {
                const float4 ab = *reinterpret_cast<const float4*>(&aggBias[tx * 8 + c4 * 4]);
                float4 w;
                w.x = v.x * d + ab.x;
                w.y = v.y * d + ab.y;
                w.z = v.z * d + ab.z;
                w.w = v.w * d + ab.w;
                *reinterpret_cast<float4*>(&agg[rowOff + c4 * 4]) = w;
            }
        }
    }
}

// ---------------------------------------------------------------------------
// edge propagate: one warp per edge; lane handles one float4 (16B) of the
// 512B feature row. Gather LDG.128 + one red.global.add.v4.f32 per lane.
// ---------------------------------------------------------------------------
__global__ __launch_bounds__(256) void edge_prop_kernel(
    long hoff, const int* __restrict__ ei, int E,
    float* __restrict__ aggext, long aggoff)
{
    const float* h = scr(hoff);
    float* agg     = aggext ? aggext : scr(aggoff);

    int warp = blockIdx.x * (blockDim.x >> 5) + (threadIdx.x >> 5);
    if (warp >= E) return;
    int lane = threadIdx.x & 31;

    int r = ei[warp];
    int c = ei[E + warp];
    float nrm = g_dinv[r] * g_dinv[c];

    float4 v = __ldg(reinterpret_cast<const float4*>(h + (size_t)r * HIDDIM) + lane);
    float* dst = agg + (size_t)c * HIDDIM + lane * 4;
    asm volatile("red.global.add.v4.f32 [%0], {%1, %2, %3, %4};"
                 :: "l"(dst), "f"(v.x * nrm), "f"(v.y * nrm),
                    "f"(v.z * nrm), "f"(v.w * nrm)
                 : "memory");
}

// ---------------------------------------------------------------------------
// launch — kernels only, no runtime API calls
// ---------------------------------------------------------------------------
extern "C" void kernel_launch(void* const* d_in, const int* in_sizes, int n_in,
                              void* d_out, int out_size)
{
    const float* x  = (const float*)d_in[0];
    const int*   ei = (const int*)d_in[1];       // int32 edge index
    const float* W1 = (const float*)d_in[2];
    const float* b1 = (const float*)d_in[3];
    const float* W2 = (const float*)d_in[4];
    const float* b2 = (const float*)d_in[5];
    const float* Wp = (const float*)d_in[6];
    const float* bp = (const float*)d_in[7];

    int N = in_sizes[0] / INDIM;          // 100000
    int E = in_sizes[1] / 2;              // 1600000

    float* z    = (float*)d_out;                       // first output: z2 [N,128]
    float* proj = z + (size_t)N * HIDDIM;              // second output

    const int T = 256;
    int nBlocksN    = (N + T - 1) / T;
    int nBlocksE    = (E + T - 1) / T;
    int nBlocksGemm = (N + 127) / 128;
    int nBlocksEdge = (E + 7) / 8;        // 8 warps per block

    // degrees + normalization (shared by both layers)
    zero_deg_kernel<<<nBlocksN, T>>>(N);
    count_deg_kernel<<<nBlocksE, T>>>(ei, E);
    dinv_kernel<<<nBlocksN, T>>>(N);

    // layer 1: h1 = x @ W1 ; z1 init = h1*dinv^2 + b1 (fused) ; edge prop
    gemm128_kernel<<<nBlocksGemm, T>>>(x, 0, W1, nullptr, OFF_H1, nullptr,
                                       nullptr, OFF_Z1, 1, b1, N, INDIM);
    edge_prop_kernel<<<nBlocksEdge, T>>>(OFF_H1, ei, E, nullptr, OFF_Z1);

    // layer 2: h2 = z1 @ W2 ; z init (in d_out) fused ; edge prop
    gemm128_kernel<<<nBlocksGemm, T>>>(nullptr, OFF_Z1, W2, nullptr, OFF_H2, nullptr,
                                       z, 0, 1, b2, N, HIDDIM);
    edge_prop_kernel<<<nBlocksEdge, T>>>(OFF_H2, ei, E, z, 0);

    // projection head: proj = z @ Wp + bp
    gemm128_kernel<<<nBlocksGemm, T>>>(z, 0, Wp, proj, 0, bp,
                                       nullptr, 0, 0, nullptr, N, HIDDIM);
}

// round 7
// speedup vs baseline: 2.1478x; 1.2443x over previous
#include <cuda_runtime.h>
#include <cstdint>

#define NNODES 100000
#define HIDDIM 128
#define INDIM  256
#define MAXE   1600000
#define NF ((long)NNODES * HIDDIM)        // 12,800,000 floats per buffer

// Scratch (static device globals — no allocation allowed)
__device__ float4 g_scratch[3 * NF / 4];  // h1, z1, h2
__device__ int    g_deg[NNODES];
__device__ float  g_dinv[NNODES];
__device__ int    g_rowStart[NNODES + 1]; // CSR offsets (by target node)
__device__ int    g_cursor[NNODES];
__device__ int    g_src[MAXE];            // source node per CSR slot

__device__ __forceinline__ float* scr(long off) {
    return reinterpret_cast<float*>(g_scratch) + off;
}

#define OFF_H1 ((long)0)
#define OFF_Z1 (NF)
#define OFF_H2 (2 * NF)

// ---------------------------------------------------------------------------
// degree / norm
// ---------------------------------------------------------------------------
__global__ void zero_deg_kernel(int n) {
    int i = blockIdx.x * blockDim.x + threadIdx.x;
    if (i < n) g_deg[i] = 0;
}

__global__ void count_deg_kernel(const int* __restrict__ ei, int E) {
    int e = blockIdx.x * blockDim.x + threadIdx.x;
    if (e < E) atomicAdd(&g_deg[ei[E + e]], 1);
}

__global__ void dinv_kernel(int n) {
    int i = blockIdx.x * blockDim.x + threadIdx.x;
    if (i < n) g_dinv[i] = rsqrtf((float)(g_deg[i] + 1));
}

// ---------------------------------------------------------------------------
// single-block exclusive scan of g_deg -> g_rowStart, and init g_cursor
// ---------------------------------------------------------------------------
__global__ __launch_bounds__(1024) void scan_kernel(int n) {
    __shared__ int sh[1024];
    int tid = threadIdx.x;
    int carry = 0;
    for (int base = 0; base < n; base += 1024) {
        int i = base + tid;
        int v = (i < n) ? g_deg[i] : 0;
        sh[tid] = v;
        __syncthreads();
        for (int off = 1; off < 1024; off <<= 1) {
            int t = (tid >= off) ? sh[tid - off] : 0;
            __syncthreads();
            sh[tid] += t;
            __syncthreads();
        }
        if (i < n) g_rowStart[i + 1] = carry + sh[tid];
        carry += sh[1023];
        __syncthreads();
    }
    if (tid == 0) g_rowStart[0] = 0;
}

__global__ void cursor_init_kernel(int n) {
    int i = blockIdx.x * blockDim.x + threadIdx.x;
    if (i < n) g_cursor[i] = g_rowStart[i];
}

__global__ void scatter_kernel(const int* __restrict__ ei, int E) {
    int e = blockIdx.x * blockDim.x + threadIdx.x;
    if (e < E) {
        int r = ei[e];
        int c = ei[E + e];
        int pos = atomicAdd(&g_cursor[c], 1);
        g_src[pos] = r;
    }
}

// ---------------------------------------------------------------------------
// GEMM: C[M,128] = A[M,K] @ B[K,128] (+ bias). BM=128 BN=128 BK=8, 8x8 tile.
// ---------------------------------------------------------------------------
__global__ __launch_bounds__(256, 2) void gemm128_kernel(
    const float* __restrict__ Aext, long aoff,
    const float* __restrict__ B,
    float* __restrict__ Cext, long coff,
    const float* __restrict__ cBias,
    int M, int K)
{
    const float* A = Aext ? Aext : scr(aoff);
    float*       C = Cext ? Cext : scr(coff);

    const int BM = 128, BN = 128, BK = 8;
    __shared__ float As[BK][BM + 4];
    __shared__ float Bs[BK][BN];

    int tid = threadIdx.x;
    int tx = tid & 15;          // 16 col groups of 8
    int ty = tid >> 4;          // 16 row groups of 8
    int m0 = blockIdx.x * BM;

    int la_m = tid >> 1;
    int la_k = (tid & 1) * 4;
    int lb_k = tid >> 5;
    int lb_n = (tid & 31) * 4;

    float acc[8][8];
#pragma unroll
    for (int r = 0; r < 8; r++)
#pragma unroll
        for (int c = 0; c < 8; c++) acc[r][c] = 0.f;

    for (int k0 = 0; k0 < K; k0 += BK) {
        {
            int gm = m0 + la_m;
            float4 v = make_float4(0.f, 0.f, 0.f, 0.f);
            if (gm < M)
                v = *reinterpret_cast<const float4*>(&A[(size_t)gm * K + k0 + la_k]);
            As[la_k + 0][la_m] = v.x;
            As[la_k + 1][la_m] = v.y;
            As[la_k + 2][la_m] = v.z;
            As[la_k + 3][la_m] = v.w;
        }
        {
            float4 v = *reinterpret_cast<const float4*>(&B[(size_t)(k0 + lb_k) * BN + lb_n]);
            *reinterpret_cast<float4*>(&Bs[lb_k][lb_n]) = v;
        }
        __syncthreads();

#pragma unroll
        for (int k = 0; k < BK; k++) {
            float a[8], bv[8];
            *reinterpret_cast<float4*>(a)      = *reinterpret_cast<const float4*>(&As[k][ty * 8]);
            *reinterpret_cast<float4*>(a + 4)  = *reinterpret_cast<const float4*>(&As[k][ty * 8 + 4]);
            *reinterpret_cast<float4*>(bv)     = *reinterpret_cast<const float4*>(&Bs[k][tx * 8]);
            *reinterpret_cast<float4*>(bv + 4) = *reinterpret_cast<const float4*>(&Bs[k][tx * 8 + 4]);
#pragma unroll
            for (int r = 0; r < 8; r++)
#pragma unroll
                for (int c = 0; c < 8; c++) acc[r][c] += a[r] * bv[c];
        }
        __syncthreads();
    }

#pragma unroll
    for (int r = 0; r < 8; r++) {
        int gm = m0 + ty * 8 + r;
        if (gm >= M) break;
        size_t rowOff = (size_t)gm * BN + tx * 8;
#pragma unroll
        for (int c4 = 0; c4 < 2; c4++) {
            float4 v;
            v.x = acc[r][c4 * 4 + 0];
            v.y = acc[r][c4 * 4 + 1];
            v.z = acc[r][c4 * 4 + 2];
            v.w = acc[r][c4 * 4 + 3];
            if (cBias) {
                const float4 bb = *reinterpret_cast<const float4*>(&cBias[tx * 8 + c4 * 4]);
                v.x += bb.x; v.y += bb.y; v.z += bb.z; v.w += bb.w;
            }
            *reinterpret_cast<float4*>(&C[rowOff + c4 * 4]) = v;
        }
    }
}

// ---------------------------------------------------------------------------
// CSR aggregate: one warp per target node c; lane owns 4 features.
//   out[c] = dinv[c] * ( sum_{r in N(c)} dinv[r]*h[r] + dinv[c]*h[c] ) + b
// No atomics: each output row written exactly once, coalesced float4.
// ---------------------------------------------------------------------------
__global__ __launch_bounds__(256) void csr_agg_kernel(
    long hoff, const float* __restrict__ bias,
    float* __restrict__ outExt, long outOff, int N)
{
    const float* h = scr(hoff);
    float* out     = outExt ? outExt : scr(outOff);

    int c = blockIdx.x * (blockDim.x >> 5) + (threadIdx.x >> 5);
    if (c >= N) return;
    int lane = threadIdx.x & 31;

    float dc = g_dinv[c];
    int start = g_rowStart[c];
    int end   = g_rowStart[c + 1];

    // self loop
    float4 acc = __ldg(reinterpret_cast<const float4*>(h + (size_t)c * HIDDIM) + lane);
    acc.x *= dc; acc.y *= dc; acc.z *= dc; acc.w *= dc;

    int j = start;
    // 4-wide software pipeline for MLP
    for (; j + 4 <= end; j += 4) {
        int r0 = __ldg(&g_src[j + 0]);
        int r1 = __ldg(&g_src[j + 1]);
        int r2 = __ldg(&g_src[j + 2]);
        int r3 = __ldg(&g_src[j + 3]);
        float s0 = __ldg(&g_dinv[r0]);
        float s1 = __ldg(&g_dinv[r1]);
        float s2 = __ldg(&g_dinv[r2]);
        float s3 = __ldg(&g_dinv[r3]);
        float4 v0 = __ldg(reinterpret_cast<const float4*>(h + (size_t)r0 * HIDDIM) + lane);
        float4 v1 = __ldg(reinterpret_cast<const float4*>(h + (size_t)r1 * HIDDIM) + lane);
        float4 v2 = __ldg(reinterpret_cast<const float4*>(h + (size_t)r2 * HIDDIM) + lane);
        float4 v3 = __ldg(reinterpret_cast<const float4*>(h + (size_t)r3 * HIDDIM) + lane);
        acc.x += s0 * v0.x + s1 * v1.x + s2 * v2.x + s3 * v3.x;
        acc.y += s0 * v0.y + s1 * v1.y + s2 * v2.y + s3 * v3.y;
        acc.z += s0 * v0.z + s1 * v1.z + s2 * v2.z + s3 * v3.z;
        acc.w += s0 * v0.w + s1 * v1.w + s2 * v2.w + s3 * v3.w;
    }
    for (; j < end; j++) {
        int r = __ldg(&g_src[j]);
        float s = __ldg(&g_dinv[r]);
        float4 v = __ldg(reinterpret_cast<const float4*>(h + (size_t)r * HIDDIM) + lane);
        acc.x += s * v.x; acc.y += s * v.y; acc.z += s * v.z; acc.w += s * v.w;
    }

    const float4 bb = __ldg(reinterpret_cast<const float4*>(bias) + lane);
    float4 o;
    o.x = acc.x * dc + bb.x;
    o.y = acc.y * dc + bb.y;
    o.z = acc.z * dc + bb.z;
    o.w = acc.w * dc + bb.w;
    reinterpret_cast<float4*>(out + (size_t)c * HIDDIM)[lane] = o;
}

// ---------------------------------------------------------------------------
// launch — kernels only, no runtime API calls
// ---------------------------------------------------------------------------
extern "C" void kernel_launch(void* const* d_in, const int* in_sizes, int n_in,
                              void* d_out, int out_size)
{
    const float* x  = (const float*)d_in[0];
    const int*   ei = (const int*)d_in[1];       // int32 edge index
    const float* W1 = (const float*)d_in[2];
    const float* b1 = (const float*)d_in[3];
    const float* W2 = (const float*)d_in[4];
    const float* b2 = (const float*)d_in[5];
    const float* Wp = (const float*)d_in[6];
    const float* bp = (const float*)d_in[7];

    int N = in_sizes[0] / INDIM;          // 100000
    int E = in_sizes[1] / 2;              // 1600000

    float* z    = (float*)d_out;                       // z2 [N,128]
    float* proj = z + (size_t)N * HIDDIM;              // projection

    const int T = 256;
    int nBlocksN    = (N + T - 1) / T;
    int nBlocksE    = (E + T - 1) / T;
    int nBlocksGemm = (N + 127) / 128;
    int nBlocksWarp = (N + 7) / 8;        // warp per node, 8 warps/block

    // ---- preprocessing: degrees, dinv, CSR by target ----
    zero_deg_kernel<<<nBlocksN, T>>>(N);
    count_deg_kernel<<<nBlocksE, T>>>(ei, E);
    dinv_kernel<<<nBlocksN, T>>>(N);
    scan_kernel<<<1, 1024>>>(N);
    cursor_init_kernel<<<nBlocksN, T>>>(N);
    scatter_kernel<<<nBlocksE, T>>>(ei, E);

    // layer 1: h1 = x @ W1 ; z1 = csr_agg(h1) + b1
    gemm128_kernel<<<nBlocksGemm, T>>>(x, 0, W1, nullptr, OFF_H1, nullptr, N, INDIM);
    csr_agg_kernel<<<nBlocksWarp, T>>>(OFF_H1, b1, nullptr, OFF_Z1, N);

    // layer 2: h2 = z1 @ W2 ; z = csr_agg(h2) + b2  (into d_out)
    gemm128_kernel<<<nBlocksGemm, T>>>(nullptr, OFF_Z1, W2, nullptr, OFF_H2, nullptr, N, HIDDIM);
    csr_agg_kernel<<<nBlocksWarp, T>>>(OFF_H2, b2, z, 0, N);

    // projection head: proj = z @ Wp + bp
    gemm128_kernel<<<nBlocksGemm, T>>>(z, 0, Wp, proj, 0, bp, N, HIDDIM);
}

// round 8
// speedup vs baseline: 2.6092x; 1.2148x over previous
#include <cuda_runtime.h>
#include <cstdint>

#define NNODES 100000
#define HIDDIM 128
#define INDIM  256
#define MAXE   1600000
#define NF ((long)NNODES * HIDDIM)        // 12,800,000 floats per buffer

// Scratch (static device globals — no allocation allowed)
__device__ float4 g_scratch[3 * NF / 4];  // h1, z1, h2
__device__ int    g_deg[NNODES];
__device__ float  g_dinv[NNODES];
__device__ int    g_rowStart[NNODES + 1]; // CSR offsets (by target node)
__device__ int    g_cursor[NNODES];
__device__ int    g_src[MAXE];            // source node per CSR slot
__device__ int    g_blockSums[256];

__device__ __forceinline__ float* scr(long off) {
    return reinterpret_cast<float*>(g_scratch) + off;
}

#define OFF_H1 ((long)0)
#define OFF_Z1 (NF)
#define OFF_H2 (2 * NF)

// ---------------------------------------------------------------------------
// degree / norm
// ---------------------------------------------------------------------------
__global__ void zero_deg_kernel(int n) {
    int i = blockIdx.x * blockDim.x + threadIdx.x;
    if (i < n) g_deg[i] = 0;
}

__global__ void count_deg_kernel(const int* __restrict__ ei, int E) {
    int e = blockIdx.x * blockDim.x + threadIdx.x;
    if (e < E) atomicAdd(&g_deg[ei[E + e]], 1);
}

__global__ void dinv_kernel(int n) {
    int i = blockIdx.x * blockDim.x + threadIdx.x;
    if (i < n) g_dinv[i] = rsqrtf((float)(g_deg[i] + 1));
}

// ---------------------------------------------------------------------------
// 3-phase scan: per-block inclusive scan, scan of block sums, offset add.
// ---------------------------------------------------------------------------
__global__ __launch_bounds__(1024) void scanA_kernel(int n) {
    __shared__ int warpSums[32];
    int tid  = threadIdx.x;
    int lane = tid & 31;
    int wid  = tid >> 5;
    int i = blockIdx.x * 1024 + tid;

    int v = (i < n) ? g_deg[i] : 0;
    // warp inclusive scan
    int s = v;
#pragma unroll
    for (int off = 1; off < 32; off <<= 1) {
        int t = __shfl_up_sync(0xffffffff, s, off);
        if (lane >= off) s += t;
    }
    if (lane == 31) warpSums[wid] = s;
    __syncthreads();
    if (wid == 0) {
        int ws = warpSums[lane];
#pragma unroll
        for (int off = 1; off < 32; off <<= 1) {
            int t = __shfl_up_sync(0xffffffff, ws, off);
            if (lane >= off) ws += t;
        }
        warpSums[lane] = ws;
    }
    __syncthreads();
    int blockPrefix = (wid > 0) ? warpSums[wid - 1] : 0;
    int incl = s + blockPrefix;
    if (i < n) g_rowStart[i + 1] = incl;
    if (tid == 1023) g_blockSums[blockIdx.x] = incl;
}

__global__ __launch_bounds__(128) void scanB_kernel(int nBlocks) {
    // single block of 128 threads; nBlocks <= 128
    __shared__ int sh[128];
    int tid = threadIdx.x;
    int v = (tid < nBlocks) ? g_blockSums[tid] : 0;
    sh[tid] = v;
    __syncthreads();
    for (int off = 1; off < 128; off <<= 1) {
        int t = (tid >= off) ? sh[tid - off] : 0;
        __syncthreads();
        sh[tid] += t;
        __syncthreads();
    }
    // exclusive
    if (tid < nBlocks) g_blockSums[tid] = (tid > 0) ? sh[tid - 1] : 0;
}

__global__ __launch_bounds__(1024) void scanC_kernel(int n) {
    int i = blockIdx.x * 1024 + threadIdx.x;
    int off = g_blockSums[blockIdx.x];
    if (i < n) g_rowStart[i + 1] += off;
    if (i == 0) g_rowStart[0] = 0;
}

__global__ void cursor_init_kernel(int n) {
    int i = blockIdx.x * blockDim.x + threadIdx.x;
    if (i < n) g_cursor[i] = g_rowStart[i];
}

__global__ void scatter_kernel(const int* __restrict__ ei, int E) {
    int e = blockIdx.x * blockDim.x + threadIdx.x;
    if (e < E) {
        int r = ei[e];
        int c = ei[E + e];
        int pos = atomicAdd(&g_cursor[c], 1);
        g_src[pos] = r;
    }
}

// ---------------------------------------------------------------------------
// GEMM: C[M,128] = A[M,K] @ B[K,128] (+ bias). BM=128 BN=128 BK=8, 8x8 tile.
// ---------------------------------------------------------------------------
__global__ __launch_bounds__(256, 2) void gemm128_kernel(
    const float* __restrict__ Aext, long aoff,
    const float* __restrict__ B,
    float* __restrict__ Cext, long coff,
    const float* __restrict__ cBias,
    int M, int K)
{
    const float* A = Aext ? Aext : scr(aoff);
    float*       C = Cext ? Cext : scr(coff);

    const int BM = 128, BN = 128, BK = 8;
    __shared__ float As[BK][BM + 4];
    __shared__ float Bs[BK][BN + 4];     // pad breaks 4-way bank conflict

    int tid = threadIdx.x;
    int tx = tid & 15;          // 16 col groups of 8
    int ty = tid >> 4;          // 16 row groups of 8
    int m0 = blockIdx.x * BM;

    int la_m = tid >> 1;
    int la_k = (tid & 1) * 4;
    int lb_k = tid >> 5;
    int lb_n = (tid & 31) * 4;

    float acc[8][8];
#pragma unroll
    for (int r = 0; r < 8; r++)
#pragma unroll
        for (int c = 0; c < 8; c++) acc[r][c] = 0.f;

    for (int k0 = 0; k0 < K; k0 += BK) {
        {
            int gm = m0 + la_m;
            float4 v = make_float4(0.f, 0.f, 0.f, 0.f);
            if (gm < M)
                v = *reinterpret_cast<const float4*>(&A[(size_t)gm * K + k0 + la_k]);
            As[la_k + 0][la_m] = v.x;
            As[la_k + 1][la_m] = v.y;
            As[la_k + 2][la_m] = v.z;
            As[la_k + 3][la_m] = v.w;
        }
        {
            float4 v = *reinterpret_cast<const float4*>(&B[(size_t)(k0 + lb_k) * BN + lb_n]);
            *reinterpret_cast<float4*>(&Bs[lb_k][lb_n]) = v;
        }
        __syncthreads();

#pragma unroll
        for (int k = 0; k < BK; k++) {
            float a[8], bv[8];
            *reinterpret_cast<float4*>(a)      = *reinterpret_cast<const float4*>(&As[k][ty * 8]);
            *reinterpret_cast<float4*>(a + 4)  = *reinterpret_cast<const float4*>(&As[k][ty * 8 + 4]);
            *reinterpret_cast<float4*>(bv)     = *reinterpret_cast<const float4*>(&Bs[k][tx * 8]);
            *reinterpret_cast<float4*>(bv + 4) = *reinterpret_cast<const float4*>(&Bs[k][tx * 8 + 4]);
#pragma unroll
            for (int r = 0; r < 8; r++)
#pragma unroll
                for (int c = 0; c < 8; c++) acc[r][c] += a[r] * bv[c];
        }
        __syncthreads();
    }

#pragma unroll
    for (int r = 0; r < 8; r++) {
        int gm = m0 + ty * 8 + r;
        if (gm >= M) break;
        size_t rowOff = (size_t)gm * BN + tx * 8;
#pragma unroll
        for (int c4 = 0; c4 < 2; c4++) {
            float4 v;
            v.x = acc[r][c4 * 4 + 0];
            v.y = acc[r][c4 * 4 + 1];
            v.z = acc[r][c4 * 4 + 2];
            v.w = acc[r][c4 * 4 + 3];
            if (cBias) {
                const float4 bb = *reinterpret_cast<const float4*>(&cBias[tx * 8 + c4 * 4]);
                v.x += bb.x; v.y += bb.y; v.z += bb.z; v.w += bb.w;
            }
            *reinterpret_cast<float4*>(&C[rowOff + c4 * 4]) = v;
        }
    }
}

// ---------------------------------------------------------------------------
// CSR aggregate: one warp per target node c; lane owns 4 features.
//   out[c] = dinv[c] * ( sum_{r in N(c)} dinv[r]*h[r] + dinv[c]*h[c] ) + b
// ---------------------------------------------------------------------------
__global__ __launch_bounds__(256) void csr_agg_kernel(
    long hoff, const float* __restrict__ bias,
    float* __restrict__ outExt, long outOff, int N)
{
    const float* h = scr(hoff);
    float* out     = outExt ? outExt : scr(outOff);

    int c = blockIdx.x * (blockDim.x >> 5) + (threadIdx.x >> 5);
    if (c >= N) return;
    int lane = threadIdx.x & 31;

    float dc = g_dinv[c];
    int start = g_rowStart[c];
    int end   = g_rowStart[c + 1];

    // self loop
    float4 acc = __ldg(reinterpret_cast<const float4*>(h + (size_t)c * HIDDIM) + lane);
    acc.x *= dc; acc.y *= dc; acc.z *= dc; acc.w *= dc;

    int j = start;
    for (; j + 4 <= end; j += 4) {
        int r0 = __ldg(&g_src[j + 0]);
        int r1 = __ldg(&g_src[j + 1]);
        int r2 = __ldg(&g_src[j + 2]);
        int r3 = __ldg(&g_src[j + 3]);
        float s0 = __ldg(&g_dinv[r0]);
        float s1 = __ldg(&g_dinv[r1]);
        float s2 = __ldg(&g_dinv[r2]);
        float s3 = __ldg(&g_dinv[r3]);
        float4 v0 = __ldg(reinterpret_cast<const float4*>(h + (size_t)r0 * HIDDIM) + lane);
        float4 v1 = __ldg(reinterpret_cast<const float4*>(h + (size_t)r1 * HIDDIM) + lane);
        float4 v2 = __ldg(reinterpret_cast<const float4*>(h + (size_t)r2 * HIDDIM) + lane);
        float4 v3 = __ldg(reinterpret_cast<const float4*>(h + (size_t)r3 * HIDDIM) + lane);
        acc.x += s0 * v0.x + s1 * v1.x + s2 * v2.x + s3 * v3.x;
        acc.y += s0 * v0.y + s1 * v1.y + s2 * v2.y + s3 * v3.y;
        acc.z += s0 * v0.z + s1 * v1.z + s2 * v2.z + s3 * v3.z;
        acc.w += s0 * v0.w + s1 * v1.w + s2 * v2.w + s3 * v3.w;
    }
    for (; j < end; j++) {
        int r = __ldg(&g_src[j]);
        float s = __ldg(&g_dinv[r]);
        float4 v = __ldg(reinterpret_cast<const float4*>(h + (size_t)r * HIDDIM) + lane);
        acc.x += s * v.x; acc.y += s * v.y; acc.z += s * v.z; acc.w += s * v.w;
    }

    const float4 bb = __ldg(reinterpret_cast<const float4*>(bias) + lane);
    float4 o;
    o.x = acc.x * dc + bb.x;
    o.y = acc.y * dc + bb.y;
    o.z = acc.z * dc + bb.z;
    o.w = acc.w * dc + bb.w;
    reinterpret_cast<float4*>(out + (size_t)c * HIDDIM)[lane] = o;
}

// ---------------------------------------------------------------------------
// launch — kernels only, no runtime API calls
// ---------------------------------------------------------------------------
extern "C" void kernel_launch(void* const* d_in, const int* in_sizes, int n_in,
                              void* d_out, int out_size)
{
    const float* x  = (const float*)d_in[0];
    const int*   ei = (const int*)d_in[1];       // int32 edge index
    const float* W1 = (const float*)d_in[2];
    const float* b1 = (const float*)d_in[3];
    const float* W2 = (const float*)d_in[4];
    const float* b2 = (const float*)d_in[5];
    const float* Wp = (const float*)d_in[6];
    const float* bp = (const float*)d_in[7];

    int N = in_sizes[0] / INDIM;          // 100000
    int E = in_sizes[1] / 2;              // 1600000

    float* z    = (float*)d_out;                       // z2 [N,128]
    float* proj = z + (size_t)N * HIDDIM;              // projection

    const int T = 256;
    int nBlocksN    = (N + T - 1) / T;
    int nBlocksE    = (E + T - 1) / T;
    int nBlocksGemm = (N + 127) / 128;
    int nBlocksWarp = (N + 7) / 8;        // warp per node, 8 warps/block
    int nScanBlocks = (N + 1023) / 1024;  // 98

    // ---- preprocessing: degrees, dinv, CSR by target ----
    zero_deg_kernel<<<nBlocksN, T>>>(N);
    count_deg_kernel<<<nBlocksE, T>>>(ei, E);
    dinv_kernel<<<nBlocksN, T>>>(N);
    scanA_kernel<<<nScanBlocks, 1024>>>(N);
    scanB_kernel<<<1, 128>>>(nScanBlocks);
    scanC_kernel<<<nScanBlocks, 1024>>>(N);
    cursor_init_kernel<<<nBlocksN, T>>>(N);
    scatter_kernel<<<nBlocksE, T>>>(ei, E);

    // layer 1: h1 = x @ W1 ; z1 = csr_agg(h1) + b1
    gemm128_kernel<<<nBlocksGemm, T>>>(x, 0, W1, nullptr, OFF_H1, nullptr, N, INDIM);
    csr_agg_kernel<<<nBlocksWarp, T>>>(OFF_H1, b1, nullptr, OFF_Z1, N);

    // layer 2: h2 = z1 @ W2 ; z = csr_agg(h2) + b2  (into d_out)
    gemm128_kernel<<<nBlocksGemm, T>>>(nullptr, OFF_Z1, W2, nullptr, OFF_H2, nullptr, N, HIDDIM);
    csr_agg_kernel<<<nBlocksWarp, T>>>(OFF_H2, b2, z, 0, N);

    // projection head: proj = z @ Wp + bp
    gemm128_kernel<<<nBlocksGemm, T>>>(z, 0, Wp, proj, 0, bp, N, HIDDIM);
}

// round 9
// speedup vs baseline: 3.8293x; 1.4676x over previous
#include <cuda_runtime.h>
#include <cuda_bf16.h>
#include <mma.h>
#include <cstdint>

using namespace nvcuda;

#define NNODES 100000
#define HIDDIM 128
#define INDIM  256
#define MAXE   1600000
#define NF ((long)NNODES * HIDDIM)        // 12,800,000 floats per buffer

// Scratch (static device globals — no allocation allowed)
__device__ float4 g_scratch[3 * NF / 4];  // h1, z1, h2
__device__ int    g_deg[NNODES];
__device__ float  g_dinv[NNODES];
__device__ int    g_rowStart[NNODES + 1]; // CSR offsets (by target node)
__device__ int    g_cursor[NNODES];
__device__ int    g_src[MAXE];            // source node per CSR slot
__device__ int    g_blockSums[256];
// split-precision weights: W1(32768) | W2(16384) | Wp(16384)
__device__ __nv_bfloat16 g_whi[65536];
__device__ __nv_bfloat16 g_wlo[65536];

__device__ __forceinline__ float* scr(long off) {
    return reinterpret_cast<float*>(g_scratch) + off;
}

#define OFF_H1 ((long)0)
#define OFF_Z1 (NF)
#define OFF_H2 (2 * NF)
#define WOFF_W1 0
#define WOFF_W2 32768
#define WOFF_WP 49152

// ---------------------------------------------------------------------------
// degree / norm
// ---------------------------------------------------------------------------
__global__ void zero_deg_kernel(int n) {
    int i = blockIdx.x * blockDim.x + threadIdx.x;
    if (i < n) g_deg[i] = 0;
}

__global__ void count_deg_kernel(const int* __restrict__ ei, int E) {
    int e = blockIdx.x * blockDim.x + threadIdx.x;
    if (e < E) atomicAdd(&g_deg[ei[E + e]], 1);
}

__global__ void dinv_kernel(int n) {
    int i = blockIdx.x * blockDim.x + threadIdx.x;
    if (i < n) g_dinv[i] = rsqrtf((float)(g_deg[i] + 1));
}

// ---------------------------------------------------------------------------
// weight split: W -> hi + lo bf16
// ---------------------------------------------------------------------------
__global__ void convert_w_kernel(const float* __restrict__ W, long off, int n) {
    int i = blockIdx.x * blockDim.x + threadIdx.x;
    if (i < n) {
        float v = W[i];
        __nv_bfloat16 hi = __float2bfloat16(v);
        __nv_bfloat16 lo = __float2bfloat16(v - __bfloat162float(hi));
        g_whi[off + i] = hi;
        g_wlo[off + i] = lo;
    }
}

// ---------------------------------------------------------------------------
// 3-phase scan
// ---------------------------------------------------------------------------
__global__ __launch_bounds__(1024) void scanA_kernel(int n) {
    __shared__ int warpSums[32];
    int tid  = threadIdx.x;
    int lane = tid & 31;
    int wid  = tid >> 5;
    int i = blockIdx.x * 1024 + tid;

    int v = (i < n) ? g_deg[i] : 0;
    int s = v;
#pragma unroll
    for (int off = 1; off < 32; off <<= 1) {
        int t = __shfl_up_sync(0xffffffff, s, off);
        if (lane >= off) s += t;
    }
    if (lane == 31) warpSums[wid] = s;
    __syncthreads();
    if (wid == 0) {
        int ws = warpSums[lane];
#pragma unroll
        for (int off = 1; off < 32; off <<= 1) {
            int t = __shfl_up_sync(0xffffffff, ws, off);
            if (lane >= off) ws += t;
        }
        warpSums[lane] = ws;
    }
    __syncthreads();
    int blockPrefix = (wid > 0) ? warpSums[wid - 1] : 0;
    int incl = s + blockPrefix;
    if (i < n) g_rowStart[i + 1] = incl;
    if (tid == 1023) g_blockSums[blockIdx.x] = incl;
}

__global__ __launch_bounds__(128) void scanB_kernel(int nBlocks) {
    __shared__ int sh[128];
    int tid = threadIdx.x;
    int v = (tid < nBlocks) ? g_blockSums[tid] : 0;
    sh[tid] = v;
    __syncthreads();
    for (int off = 1; off < 128; off <<= 1) {
        int t = (tid >= off) ? sh[tid - off] : 0;
        __syncthreads();
        sh[tid] += t;
        __syncthreads();
    }
    if (tid < nBlocks) g_blockSums[tid] = (tid > 0) ? sh[tid - 1] : 0;
}

__global__ __launch_bounds__(1024) void scanC_kernel(int n) {
    int i = blockIdx.x * 1024 + threadIdx.x;
    int off = g_blockSums[blockIdx.x];
    if (i < n) g_rowStart[i + 1] += off;
    if (i == 0) g_rowStart[0] = 0;
}

__global__ void cursor_init_kernel(int n) {
    int i = blockIdx.x * blockDim.x + threadIdx.x;
    if (i < n) g_cursor[i] = g_rowStart[i];
}

__global__ void scatter_kernel(const int* __restrict__ ei, int E) {
    int e = blockIdx.x * blockDim.x + threadIdx.x;
    if (e < E) {
        int r = ei[e];
        int c = ei[E + e];
        int pos = atomicAdd(&g_cursor[c], 1);
        g_src[pos] = r;
    }
}

// ---------------------------------------------------------------------------
// Tensor-core GEMM with bf16 split precision:
//   C = A @ W (+bias),  A fp32 [M,K], W pre-split hi/lo bf16 [K,128].
//   acc += Ahi*Whi + Ahi*Wlo + Alo*Whi  (fp32 accum, err ~1e-5)
// BM=128 BN=128 BK=16; 8 warps, each 32x64 (2x4 wmma 16x16x16 frags).
// ---------------------------------------------------------------------------
#define APITCH 24
#define BPITCH 136

__global__ __launch_bounds__(256, 2) void gemm_tc_kernel(
    const float* __restrict__ Aext, long aoff,
    long woff,
    float* __restrict__ Cext, long coff,
    const float* __restrict__ cBias,
    int M, int K)
{
    const float* A = Aext ? Aext : scr(aoff);
    float*       C = Cext ? Cext : scr(coff);

    // smem: As_hi(6144) As_lo(6144) Bs_hi(4352) Bs_lo(4352) = 20992
    // stage: 8 warps * 16*64*4 = 32768  (union)
    __shared__ __align__(16) char smemRaw[32768];
    __nv_bfloat16* As_hi = reinterpret_cast<__nv_bfloat16*>(smemRaw);
    __nv_bfloat16* As_lo = reinterpret_cast<__nv_bfloat16*>(smemRaw + 6144);
    __nv_bfloat16* Bs_hi = reinterpret_cast<__nv_bfloat16*>(smemRaw + 12288);
    __nv_bfloat16* Bs_lo = reinterpret_cast<__nv_bfloat16*>(smemRaw + 16640);

    int tid  = threadIdx.x;
    int wid  = tid >> 5;
    int lane = tid & 31;
    int warp_m = wid & 3;        // 4 warps along M (32 rows each)
    int warp_n = wid >> 2;       // 2 warps along N (64 cols each)
    int m0 = blockIdx.x * 128;

    wmma::fragment<wmma::accumulator, 16, 16, 16, float> acc[2][4];
#pragma unroll
    for (int i = 0; i < 2; i++)
#pragma unroll
        for (int j = 0; j < 4; j++) wmma::fill_fragment(acc[i][j], 0.f);

    // A-load mapping: thread -> (row, colgroup of 8)
    int la_m = tid >> 1;
    int la_c = (tid & 1) * 8;
    // B-load mapping: thread -> (k, group of 8 cols)
    int lb_k = tid >> 4;
    int lb_n = (tid & 15) * 8;

    const __nv_bfloat16* Whi = g_whi + woff;
    const __nv_bfloat16* Wlo = g_wlo + woff;

    for (int k0 = 0; k0 < K; k0 += 16) {
        // ---- load A tile [128x16] fp32 -> split bf16 smem ----
        {
            int gm = m0 + la_m;
            float v[8];
            if (gm < M) {
                const float* ap = &A[(size_t)gm * K + k0 + la_c];
                float4 v0 = *reinterpret_cast<const float4*>(ap);
                float4 v1 = *reinterpret_cast<const float4*>(ap + 4);
                v[0]=v0.x; v[1]=v0.y; v[2]=v0.z; v[3]=v0.w;
                v[4]=v1.x; v[5]=v1.y; v[6]=v1.z; v[7]=v1.w;
            } else {
#pragma unroll
                for (int q = 0; q < 8; q++) v[q] = 0.f;
            }
            __nv_bfloat16 hi[8], lo[8];
#pragma unroll
            for (int q = 0; q < 8; q++) {
                hi[q] = __float2bfloat16(v[q]);
                lo[q] = __float2bfloat16(v[q] - __bfloat162float(hi[q]));
            }
            *reinterpret_cast<uint4*>(&As_hi[la_m * APITCH + la_c]) = *reinterpret_cast<uint4*>(hi);
            *reinterpret_cast<uint4*>(&As_lo[la_m * APITCH + la_c]) = *reinterpret_cast<uint4*>(lo);
        }
        // ---- load B tile [16x128] bf16 hi/lo ----
        {
            size_t gOff = (size_t)(k0 + lb_k) * 128 + lb_n;
            *reinterpret_cast<uint4*>(&Bs_hi[lb_k * BPITCH + lb_n]) =
                *reinterpret_cast<const uint4*>(&Whi[gOff]);
            *reinterpret_cast<uint4*>(&Bs_lo[lb_k * BPITCH + lb_n]) =
                *reinterpret_cast<const uint4*>(&Wlo[gOff]);
        }
        __syncthreads();

        // ---- mma ----
        wmma::fragment<wmma::matrix_b, 16, 16, 16, __nv_bfloat16, wmma::row_major> b_hi[4], b_lo[4];
#pragma unroll
        for (int j = 0; j < 4; j++) {
            wmma::load_matrix_sync(b_hi[j], &Bs_hi[warp_n * 64 + j * 16], BPITCH);
            wmma::load_matrix_sync(b_lo[j], &Bs_lo[warp_n * 64 + j * 16], BPITCH);
        }
#pragma unroll
        for (int i = 0; i < 2; i++) {
            wmma::fragment<wmma::matrix_a, 16, 16, 16, __nv_bfloat16, wmma::row_major> a_hi, a_lo;
            wmma::load_matrix_sync(a_hi, &As_hi[(warp_m * 32 + i * 16) * APITCH], APITCH);
            wmma::load_matrix_sync(a_lo, &As_lo[(warp_m * 32 + i * 16) * APITCH], APITCH);
#pragma unroll
            for (int j = 0; j < 4; j++) {
                wmma::mma_sync(acc[i][j], a_hi, b_hi[j], acc[i][j]);
                wmma::mma_sync(acc[i][j], a_hi, b_lo[j], acc[i][j]);
                wmma::mma_sync(acc[i][j], a_lo, b_hi[j], acc[i][j]);
            }
        }
        __syncthreads();
    }

    // ---- epilogue: stage 16x64 per warp through smem, fuse bias, guard M ----
    float* stage = reinterpret_cast<float*>(smemRaw) + wid * 16 * 64;
#pragma unroll
    for (int i = 0; i < 2; i++) {
#pragma unroll
        for (int j = 0; j < 4; j++)
            wmma::store_matrix_sync(&stage[j * 16], acc[i][j], 64, wmma::mem_row_major);
        __syncwarp();
#pragma unroll
        for (int p = 0; p < 8; p++) {
            int row = p * 2 + (lane >> 4);
            int gm = m0 + warp_m * 32 + i * 16 + row;
            if (gm < M) {
                int c4 = lane & 15;
                int gcol = warp_n * 64 + c4 * 4;
                float4 v = *reinterpret_cast<float4*>(&stage[row * 64 + c4 * 4]);
                if (cBias) {
                    float4 bb = *reinterpret_cast<const float4*>(&cBias[gcol]);
                    v.x += bb.x; v.y += bb.y; v.z += bb.z; v.w += bb.w;
                }
                *reinterpret_cast<float4*>(&C[(size_t)gm * 128 + gcol]) = v;
            }
        }
        __syncwarp();
    }
}

// ---------------------------------------------------------------------------
// CSR aggregate: one warp per target node c; lane owns 4 features.
//   out[c] = dinv[c] * ( sum_{r in N(c)} dinv[r]*h[r] + dinv[c]*h[c] ) + b
// ---------------------------------------------------------------------------
__global__ __launch_bounds__(256) void csr_agg_kernel(
    long hoff, const float* __restrict__ bias,
    float* __restrict__ outExt, long outOff, int N)
{
    const float* h = scr(hoff);
    float* out     = outExt ? outExt : scr(outOff);

    int c = blockIdx.x * (blockDim.x >> 5) + (threadIdx.x >> 5);
    if (c >= N) return;
    int lane = threadIdx.x & 31;

    float dc = g_dinv[c];
    int start = g_rowStart[c];
    int end   = g_rowStart[c + 1];

    float4 acc = __ldg(reinterpret_cast<const float4*>(h + (size_t)c * HIDDIM) + lane);
    acc.x *= dc; acc.y *= dc; acc.z *= dc; acc.w *= dc;

    int j = start;
    for (; j + 4 <= end; j += 4) {
        int r0 = __ldg(&g_src[j + 0]);
        int r1 = __ldg(&g_src[j + 1]);
        int r2 = __ldg(&g_src[j + 2]);
        int r3 = __ldg(&g_src[j + 3]);
        float s0 = __ldg(&g_dinv[r0]);
        float s1 = __ldg(&g_dinv[r1]);
        float s2 = __ldg(&g_dinv[r2]);
        float s3 = __ldg(&g_dinv[r3]);
        float4 v0 = __ldg(reinterpret_cast<const float4*>(h + (size_t)r0 * HIDDIM) + lane);
        float4 v1 = __ldg(reinterpret_cast<const float4*>(h + (size_t)r1 * HIDDIM) + lane);
        float4 v2 = __ldg(reinterpret_cast<const float4*>(h + (size_t)r2 * HIDDIM) + lane);
        float4 v3 = __ldg(reinterpret_cast<const float4*>(h + (size_t)r3 * HIDDIM) + lane);
        acc.x += s0 * v0.x + s1 * v1.x + s2 * v2.x + s3 * v3.x;
        acc.y += s0 * v0.y + s1 * v1.y + s2 * v2.y + s3 * v3.y;
        acc.z += s0 * v0.z + s1 * v1.z + s2 * v2.z + s3 * v3.z;
        acc.w += s0 * v0.w + s1 * v1.w + s2 * v2.w + s3 * v3.w;
    }
    for (; j < end; j++) {
        int r = __ldg(&g_src[j]);
        float s = __ldg(&g_dinv[r]);
        float4 v = __ldg(reinterpret_cast<const float4*>(h + (size_t)r * HIDDIM) + lane);
        acc.x += s * v.x; acc.y += s * v.y; acc.z += s * v.z; acc.w += s * v.w;
    }

    const float4 bb = __ldg(reinterpret_cast<const float4*>(bias) + lane);
    float4 o;
    o.x = acc.x * dc + bb.x;
    o.y = acc.y * dc + bb.y;
    o.z = acc.z * dc + bb.z;
    o.w = acc.w * dc + bb.w;
    reinterpret_cast<float4*>(out + (size_t)c * HIDDIM)[lane] = o;
}

// ---------------------------------------------------------------------------
// launch — kernels only, no runtime API calls
// ---------------------------------------------------------------------------
extern "C" void kernel_launch(void* const* d_in, const int* in_sizes, int n_in,
                              void* d_out, int out_size)
{
    const float* x  = (const float*)d_in[0];
    const int*   ei = (const int*)d_in[1];       // int32 edge index
    const float* W1 = (const float*)d_in[2];
    const float* b1 = (const float*)d_in[3];
    const float* W2 = (const float*)d_in[4];
    const float* b2 = (const float*)d_in[5];
    const float* Wp = (const float*)d_in[6];
    const float* bp = (const float*)d_in[7];

    int N = in_sizes[0] / INDIM;          // 100000
    int E = in_sizes[1] / 2;              // 1600000

    float* z    = (float*)d_out;                       // z2 [N,128]
    float* proj = z + (size_t)N * HIDDIM;              // projection

    const int T = 256;
    int nBlocksN    = (N + T - 1) / T;
    int nBlocksE    = (E + T - 1) / T;
    int nBlocksGemm = (N + 127) / 128;
    int nBlocksWarp = (N + 7) / 8;
    int nScanBlocks = (N + 1023) / 1024;

    // ---- preprocessing: degrees, dinv, CSR by target, weight splits ----
    zero_deg_kernel<<<nBlocksN, T>>>(N);
    count_deg_kernel<<<nBlocksE, T>>>(ei, E);
    dinv_kernel<<<nBlocksN, T>>>(N);
    scanA_kernel<<<nScanBlocks, 1024>>>(N);
    scanB_kernel<<<1, 128>>>(nScanBlocks);
    scanC_kernel<<<nScanBlocks, 1024>>>(N);
    cursor_init_kernel<<<nBlocksN, T>>>(N);
    scatter_kernel<<<nBlocksE, T>>>(ei, E);
    convert_w_kernel<<<(INDIM * HIDDIM + T - 1) / T, T>>>(W1, WOFF_W1, INDIM * HIDDIM);
    convert_w_kernel<<<(HIDDIM * HIDDIM + T - 1) / T, T>>>(W2, WOFF_W2, HIDDIM * HIDDIM);
    convert_w_kernel<<<(HIDDIM * HIDDIM + T - 1) / T, T>>>(Wp, WOFF_WP, HIDDIM * HIDDIM);

    // layer 1: h1 = x @ W1 ; z1 = csr_agg(h1) + b1
    gemm_tc_kernel<<<nBlocksGemm, T>>>(x, 0, WOFF_W1, nullptr, OFF_H1, nullptr, N, INDIM);
    csr_agg_kernel<<<nBlocksWarp, T>>>(OFF_H1, b1, nullptr, OFF_Z1, N);

    // layer 2: h2 = z1 @ W2 ; z = csr_agg(h2) + b2  (into d_out)
    gemm_tc_kernel<<<nBlocksGemm, T>>>(nullptr, OFF_Z1, WOFF_W2, nullptr, OFF_H2, nullptr, N, HIDDIM);
    csr_agg_kernel<<<nBlocksWarp, T>>>(OFF_H2, b2, z, 0, N);

    // projection head: proj = z @ Wp + bp
    gemm_tc_kernel<<<nBlocksGemm, T>>>(z, 0, WOFF_WP, proj, 0, bp, N, HIDDIM);
}